// round 10
// baseline (speedup 1.0000x reference)
#include <cuda_runtime.h>
#include <cuda_bf16.h>
#include <cstdint>

#define BWIN 2048
#define NTOK 64
#define DIM  256
#define HEADS 8
#define HD   32
#define NW   64

// ---- scratch (device globals; no allocations allowed) ----
__device__ uint32_t g_qh[BWIN*HEADS*NTOK*16];
__device__ uint32_t g_ql[BWIN*HEADS*NTOK*16];
__device__ uint32_t g_kh[BWIN*HEADS*NTOK*16];
__device__ uint32_t g_kl[BWIN*HEADS*NTOK*16];
__device__ uint32_t g_vh[BWIN*HEADS*NTOK*16];
__device__ uint32_t g_vl[BWIN*HEADS*NTOK*16];
__device__ float    g_qn[BWIN*HEADS*NTOK];
__device__ float    g_kn[BWIN*HEADS*NTOK];
// attention output pre-split bf16 h/l, [M=131072, K=256] as 128 uint32 words/row
__device__ uint32_t g_aoh[BWIN*NTOK*128];
__device__ uint32_t g_aol[BWIN*NTOK*128];
__device__ float g_bias  [HEADS*NTOK*NTOK];
__device__ float g_invtau[HEADS*NTOK*NTOK];
__device__ __nv_bfloat16 g_wbh[262144];
__device__ __nv_bfloat16 g_wbl[262144];

// ============================================================
// helpers
// ============================================================
__device__ __forceinline__ void mma16816(float* c, const uint32_t* a, const uint32_t* b) {
    asm volatile("mma.sync.aligned.m16n8k16.row.col.f32.bf16.bf16.f32 "
        "{%0,%1,%2,%3}, {%4,%5,%6,%7}, {%8,%9}, {%0,%1,%2,%3};\n"
        : "+f"(c[0]), "+f"(c[1]), "+f"(c[2]), "+f"(c[3])
        : "r"(a[0]), "r"(a[1]), "r"(a[2]), "r"(a[3]), "r"(b[0]), "r"(b[1]));
}
__device__ __forceinline__ void ldsm_x4(uint32_t* r, uint32_t addr) {
    asm volatile("ldmatrix.sync.aligned.m8n8.x4.shared.b16 {%0,%1,%2,%3}, [%4];"
        : "=r"(r[0]), "=r"(r[1]), "=r"(r[2]), "=r"(r[3]) : "r"(addr));
}
__device__ __forceinline__ void ldsm_x2(uint32_t* r, uint32_t addr) {
    asm volatile("ldmatrix.sync.aligned.m8n8.x2.shared.b16 {%0,%1}, [%2];"
        : "=r"(r[0]), "=r"(r[1]) : "r"(addr));
}
__device__ __forceinline__ void ldsm_x2t(uint32_t* r, uint32_t addr) {
    asm volatile("ldmatrix.sync.aligned.m8n8.x2.trans.shared.b16 {%0,%1}, [%2];"
        : "=r"(r[0]), "=r"(r[1]) : "r"(addr));
}
__device__ __forceinline__ void cp16(uint32_t smem, const void* gmem) {
    asm volatile("cp.async.cg.shared.global [%0], [%1], 16;" :: "r"(smem), "l"(gmem));
}
__device__ __forceinline__ void cp_commit() { asm volatile("cp.async.commit_group;"); }
__device__ __forceinline__ void cp_wait0()  { asm volatile("cp.async.wait_group 0;"); }
__device__ __forceinline__ uint32_t pack_hi(float a, float b, float& ra, float& rb) {
    __nv_bfloat16 ha = __float2bfloat16_rn(a);
    __nv_bfloat16 hb = __float2bfloat16_rn(b);
    ra = a - __bfloat162float(ha);
    rb = b - __bfloat162float(hb);
    return ((uint32_t)__bfloat16_as_ushort(hb) << 16) | (uint32_t)__bfloat16_as_ushort(ha);
}
__device__ __forceinline__ uint32_t pack2(float a, float b) {
    return ((uint32_t)__bfloat16_as_ushort(__float2bfloat16_rn(b)) << 16)
         | (uint32_t)__bfloat16_as_ushort(__float2bfloat16_rn(a));
}

// ============================================================
// Kernel 0: pre-split weights to bf16 h/l ([K,N] layout)
// ============================================================
__global__ void prep_w_kernel(const float* __restrict__ Wq,
                              const float* __restrict__ Wkv,
                              const float* __restrict__ Wp)
{
    int i = blockIdx.x * 256 + threadIdx.x;
    if (i >= 262144) return;
    float f;
    if (i < 65536) f = Wq[i];
    else if (i < 196608) f = Wkv[i - 65536];
    else f = Wp[i - 196608];
    __nv_bfloat16 hh = __float2bfloat16_rn(f);
    g_wbh[i] = hh;
    g_wbl[i] = __float2bfloat16_rn(f - __bfloat162float(hh));
}

// ============================================================
// Kernel 1: CPB bias MLP + inv-tau tables
// ============================================================
__global__ void bias_kernel(const float* __restrict__ w1, const float* __restrict__ b1,
                            const float* __restrict__ w2, const float* __restrict__ b2,
                            const float* __restrict__ tau, const float* __restrict__ lri)
{
    int idx = blockIdx.x * blockDim.x + threadIdx.x;
    if (idx >= NTOK*NTOK) return;
    float r0 = lri[idx*2 + 0];
    float r1 = lri[idx*2 + 1];
    float acc[HEADS];
    #pragma unroll
    for (int h = 0; h < HEADS; h++) acc[h] = 0.f;
    for (int k = 0; k < 256; k++) {
        float hk = fmaxf(r0 * w1[k] + r1 * w1[256 + k] + b1[k], 0.f);
        #pragma unroll
        for (int h = 0; h < HEADS; h++) acc[h] += hk * w2[k*HEADS + h];
    }
    #pragma unroll
    for (int h = 0; h < HEADS; h++) {
        g_bias[h*NTOK*NTOK + idx] = acc[h] + b2[h];
        g_invtau[h*NTOK*NTOK + idx] = 1.0f / fmaxf(tau[h*NTOK*NTOK + idx], 0.01f);
    }
}

// ============================================================
// Kernel 2: projection GEMM (R8 config, templated on MODE)
//   MODE 0: Q from x; MODE 1: KV; MODE 2: out from pre-split ao
// ============================================================
template<int MODE>
__global__ void __launch_bounds__(256, 2) mma_gemm_kernel(
    const float* __restrict__ A,
    const float* __restrict__ bias, float* __restrict__ D,
    int ldb, int woff)
{
    __shared__ alignas(16) char Bs_h[2][4096];
    __shared__ alignas(16) char Bs_l[2][4096];

    int tid = threadIdx.x;
    int lane = tid & 31, wid = tid >> 5;
    int warp_m = wid >> 1, warp_n = wid & 1;
    int row0 = blockIdx.y * 128;
    int col0 = blockIdx.x * 128;

    int k_b2 = tid >> 4;
    int n_b2 = (tid & 15) * 8;
    uint32_t offB = (uint32_t)k_b2*256u + (uint32_t)(((n_b2 >> 3) ^ (k_b2 & 7)) << 4);
    uint32_t stBh[2], stBl[2];
    #pragma unroll
    for (int s = 0; s < 2; s++) {
        stBh[s] = (uint32_t)__cvta_generic_to_shared(&Bs_h[s][0]) + offB;
        stBl[s] = (uint32_t)__cvta_generic_to_shared(&Bs_l[s][0]) + offB;
    }
    int bk_lane = lane & 15;
    uint32_t bbase_h[2], bbase_l[2];
    #pragma unroll
    for (int s = 0; s < 2; s++) {
        bbase_h[s] = (uint32_t)__cvta_generic_to_shared(&Bs_h[s][0]) + (uint32_t)bk_lane * 256u;
        bbase_l[s] = (uint32_t)__cvta_generic_to_shared(&Bs_l[s][0]) + (uint32_t)bk_lane * 256u;
    }
    int bkm = bk_lane & 7;

    const __nv_bfloat16* Bh = g_wbh + woff;
    const __nv_bfloat16* Bl = g_wbl + woff;

    // A pointers
    int arow = row0 + warp_m*32 + (lane >> 2);
    const float* ap0 = A + (size_t)arow * DIM + (lane & 3) * 2;
    const float* ap1 = ap0 + 16 * DIM;
    const uint32_t* uh0 = g_aoh + (size_t)arow * 128 + (lane & 3);
    const uint32_t* uh1 = uh0 + 16 * 128;
    const uint32_t* ul0 = g_aol + (size_t)arow * 128 + (lane & 3);
    const uint32_t* ul1 = ul0 + 16 * 128;

    float acc[2][8][4];
    #pragma unroll
    for (int mt = 0; mt < 2; mt++)
        #pragma unroll
        for (int nt = 0; nt < 8; nt++)
            #pragma unroll
            for (int i = 0; i < 4; i++) acc[mt][nt][i] = 0.f;

    // prologue
    cp16(stBh[0], Bh + (size_t)k_b2 * ldb + col0 + n_b2);
    cp16(stBl[0], Bl + (size_t)k_b2 * ldb + col0 + n_b2);
    cp_commit();

    float2 af[2][4];
    uint32_t ah[2][4], al[2][4];
    if (MODE != 2) {
        af[0][0] = *(const float2*)(ap0);
        af[0][1] = *(const float2*)(ap0 + 8*DIM);
        af[0][2] = *(const float2*)(ap0 + 8);
        af[0][3] = *(const float2*)(ap0 + 8*DIM + 8);
        af[1][0] = *(const float2*)(ap1);
        af[1][1] = *(const float2*)(ap1 + 8*DIM);
        af[1][2] = *(const float2*)(ap1 + 8);
        af[1][3] = *(const float2*)(ap1 + 8*DIM + 8);
    } else {
        ah[0][0] = uh0[0];       ah[0][1] = uh0[8*128];
        ah[0][2] = uh0[4];       ah[0][3] = uh0[8*128 + 4];
        ah[1][0] = uh1[0];       ah[1][1] = uh1[8*128];
        ah[1][2] = uh1[4];       ah[1][3] = uh1[8*128 + 4];
        al[0][0] = ul0[0];       al[0][1] = ul0[8*128];
        al[0][2] = ul0[4];       al[0][3] = ul0[8*128 + 4];
        al[1][0] = ul1[0];       al[1][1] = ul1[8*128];
        al[1][2] = ul1[4];       al[1][3] = ul1[8*128 + 4];
    }
    cp_wait0();
    __syncthreads();

    for (int kc = 0; kc < DIM/16; kc++) {
        int cur = kc & 1, nxt = cur ^ 1;
        bool has_next = (kc + 1 < DIM/16);

        if (has_next) {
            int k0 = (kc + 1) * 16;
            cp16(stBh[nxt], Bh + (size_t)(k0 + k_b2) * ldb + col0 + n_b2);
            cp16(stBl[nxt], Bl + (size_t)(k0 + k_b2) * ldb + col0 + n_b2);
            cp_commit();
        }

        if (MODE != 2) {
            #pragma unroll
            for (int mt = 0; mt < 2; mt++)
                #pragma unroll
                for (int j = 0; j < 4; j++) {
                    float rx, ry;
                    ah[mt][j] = pack_hi(af[mt][j].x, af[mt][j].y, rx, ry);
                    al[mt][j] = pack2(rx, ry);
                }
            if (has_next) {
                int kk = (kc + 1) * 16;
                af[0][0] = *(const float2*)(ap0 + kk);
                af[0][1] = *(const float2*)(ap0 + 8*DIM + kk);
                af[0][2] = *(const float2*)(ap0 + kk + 8);
                af[0][3] = *(const float2*)(ap0 + 8*DIM + kk + 8);
                af[1][0] = *(const float2*)(ap1 + kk);
                af[1][1] = *(const float2*)(ap1 + 8*DIM + kk);
                af[1][2] = *(const float2*)(ap1 + kk + 8);
                af[1][3] = *(const float2*)(ap1 + 8*DIM + kk + 8);
            }
        }

        // compute from B buffer cur (uses current ah/al)
        uint32_t cah[2][4], cal[2][4];
        #pragma unroll
        for (int mt = 0; mt < 2; mt++)
            #pragma unroll
            for (int j = 0; j < 4; j++) { cah[mt][j] = ah[mt][j]; cal[mt][j] = al[mt][j]; }

        if (MODE == 2 && has_next) {
            int kw = (kc + 1) * 8;
            ah[0][0] = uh0[kw];       ah[0][1] = uh0[8*128 + kw];
            ah[0][2] = uh0[kw + 4];   ah[0][3] = uh0[8*128 + kw + 4];
            ah[1][0] = uh1[kw];       ah[1][1] = uh1[8*128 + kw];
            ah[1][2] = uh1[kw + 4];   ah[1][3] = uh1[8*128 + kw + 4];
            al[0][0] = ul0[kw];       al[0][1] = ul0[8*128 + kw];
            al[0][2] = ul0[kw + 4];   al[0][3] = ul0[8*128 + kw + 4];
            al[1][0] = ul1[kw];       al[1][1] = ul1[8*128 + kw];
            al[1][2] = ul1[kw + 4];   al[1][3] = ul1[8*128 + kw + 4];
        }

        #pragma unroll
        for (int nt = 0; nt < 8; nt++) {
            uint32_t boff = (uint32_t)(((warp_n*8 + nt) ^ bkm) << 4);
            uint32_t bh2[2], bl2[2];
            ldsm_x2t(bh2, bbase_h[cur] + boff);
            ldsm_x2t(bl2, bbase_l[cur] + boff);
            mma16816(acc[0][nt], cah[0], bh2);
            mma16816(acc[1][nt], cah[1], bh2);
            mma16816(acc[0][nt], cah[0], bl2);
            mma16816(acc[1][nt], cah[1], bl2);
            mma16816(acc[0][nt], cal[0], bh2);
            mma16816(acc[1][nt], cal[1], bh2);
        }

        if (has_next) cp_wait0();
        __syncthreads();
    }

    // ---- epilogue ----
    if (MODE == 2) {
        #pragma unroll
        for (int mt = 0; mt < 2; mt++) {
            int r_base = row0 + warp_m*32 + mt*16 + (lane >> 2);
            #pragma unroll
            for (int nt = 0; nt < 8; nt++) {
                int c = col0 + warp_n*64 + nt*8 + 2*(lane & 3);
                float b0 = bias[c], b1 = bias[c+1];
                *(float2*)&D[(size_t)r_base*DIM + c] =
                    make_float2(acc[mt][nt][0]+b0, acc[mt][nt][1]+b1);
                *(float2*)&D[(size_t)(r_base+8)*DIM + c] =
                    make_float2(acc[mt][nt][2]+b0, acc[mt][nt][3]+b1);
            }
        }
    } else {
        const float scale = 0.17677669529663687f;
        #pragma unroll
        for (int mt = 0; mt < 2; mt++) {
            int rr = row0 + warp_m*32 + mt*16 + (lane >> 2);
            int bI = rr >> 6, nI = rr & 63;
            #pragma unroll
            for (int hg = 0; hg < 2; hg++) {
                int cg = col0 + warp_n*64 + hg*32;
                float sqA = 0.f, sqB = 0.f;
                uint32_t hwA[4], lwA[4], hwB[4], lwB[4];
                #pragma unroll
                for (int j = 0; j < 4; j++) {
                    int nt = hg*4 + j;
                    int c = cg + j*8 + 2*(lane & 3);
                    float b0 = bias[c], b1 = bias[c+1];
                    float v0 = acc[mt][nt][0]+b0, v1 = acc[mt][nt][1]+b1;
                    float v2 = acc[mt][nt][2]+b0, v3 = acc[mt][nt][3]+b1;
                    if (MODE == 0) { v0*=scale; v1*=scale; v2*=scale; v3*=scale; }
                    sqA += v0*v0 + v1*v1;
                    sqB += v2*v2 + v3*v3;
                    float rx, ry;
                    hwA[j] = pack_hi(v0, v1, rx, ry); lwA[j] = pack2(rx, ry);
                    hwB[j] = pack_hi(v2, v3, rx, ry); lwB[j] = pack2(rx, ry);
                }
                sqA += __shfl_xor_sync(0xffffffffu, sqA, 1);
                sqA += __shfl_xor_sync(0xffffffffu, sqA, 2);
                sqB += __shfl_xor_sync(0xffffffffu, sqB, 1);
                sqB += __shfl_xor_sync(0xffffffffu, sqB, 2);

                uint32_t *dh, *dl;
                float* dn = nullptr;
                int hh;
                if (MODE == 0)      { hh = cg >> 5;         dh = g_qh; dl = g_ql; dn = g_qn; }
                else if (cg < 256)  { hh = cg >> 5;         dh = g_kh; dl = g_kl; dn = g_kn; }
                else                { hh = (cg - 256) >> 5; dh = g_vh; dl = g_vl; }

                size_t wb = (((size_t)bI*HEADS + hh)*NTOK + nI)*16 + (lane & 3);
                #pragma unroll
                for (int j = 0; j < 4; j++) {
                    dh[wb + j*4]        = hwA[j];
                    dl[wb + j*4]        = lwA[j];
                    dh[wb + 8*16 + j*4] = hwB[j];
                    dl[wb + 8*16 + j*4] = lwB[j];
                }
                if (dn && (lane & 3) == 0) {
                    size_t nb = ((size_t)bI*HEADS + hh)*NTOK + nI;
                    dn[nb]     = sqrtf(sqA);
                    dn[nb + 8] = sqrtf(sqB);
                }
            }
        }
    }
}

// ============================================================
// Kernel 3: tensor-core attention, 2 windows/CTA (256 threads)
// ============================================================
#define ATTN_SMEM 50176

__global__ void __launch_bounds__(256) attn_mma_kernel(const float* __restrict__ mask)
{
    extern __shared__ char dsm[];

    int gx = blockIdx.x;                 // 0..255
    int h  = blockIdx.y;
    int w  = gx & 63, jg = gx >> 6;      // jg 0..3
    int tid = threadIdx.x;
    int lane = tid & 31, wid = tid >> 5;
    int ws = wid >> 2;                   // window slot 0/1
    int mbase = (wid & 3) * 16;

    char* qsm = dsm + ws*24576;
    char* ksm = qsm + 8192;
    char* vsm = qsm + 16384;
    float* qn_s = (float*)(dsm + 49152 + ws*512);
    float* kn_s = qn_s + 64;

    uint32_t qsb = (uint32_t)__cvta_generic_to_shared(qsm);
    uint32_t ksb = (uint32_t)__cvta_generic_to_shared(ksm);
    uint32_t vsb = (uint32_t)__cvta_generic_to_shared(vsm);

    const float* itp = g_invtau + h*4096;
    const float* bpp = g_bias   + h*4096;
    const float* mpp = mask + (size_t)w*4096;

    int tl   = tid & 127;
    int r_ld = tl >> 1;
    int half = tl & 1;
    int swr = r_ld & 7;
    int ko0 = half * 2;

    for (int t = 0; t < 4; t++) {
        int b = w + 64 * (jg * 8 + t * 2 + ws);
        size_t wb = (((size_t)b*HEADS + h)*NTOK + r_ld)*16 + half*8;
        size_t nb = ((size_t)b*HEADS + h)*NTOK;

        // ---- fill ----
        {
            uint4 a0 = *(const uint4*)(g_qh + wb);
            uint4 a1 = *(const uint4*)(g_qh + wb + 4);
            uint4 b0 = *(const uint4*)(g_ql + wb);
            uint4 b1 = *(const uint4*)(g_ql + wb + 4);
            *(uint4*)(qsm + r_ld*128 + (((ko0+0) ^ swr) << 4))     = a0;
            *(uint4*)(qsm + r_ld*128 + (((ko0+1) ^ swr) << 4))     = a1;
            *(uint4*)(qsm + r_ld*128 + (((4+ko0+0) ^ swr) << 4))   = b0;
            *(uint4*)(qsm + r_ld*128 + (((4+ko0+1) ^ swr) << 4))   = b1;
            a0 = *(const uint4*)(g_kh + wb);
            a1 = *(const uint4*)(g_kh + wb + 4);
            b0 = *(const uint4*)(g_kl + wb);
            b1 = *(const uint4*)(g_kl + wb + 4);
            *(uint4*)(ksm + r_ld*128 + (((ko0+0) ^ swr) << 4))     = a0;
            *(uint4*)(ksm + r_ld*128 + (((ko0+1) ^ swr) << 4))     = a1;
            *(uint4*)(ksm + r_ld*128 + (((4+ko0+0) ^ swr) << 4))   = b0;
            *(uint4*)(ksm + r_ld*128 + (((4+ko0+1) ^ swr) << 4))   = b1;
            a0 = *(const uint4*)(g_vh + wb);
            a1 = *(const uint4*)(g_vh + wb + 4);
            b0 = *(const uint4*)(g_vl + wb);
            b1 = *(const uint4*)(g_vl + wb + 4);
            *(uint4*)(vsm + r_ld*128 + (((ko0+0) ^ swr) << 4))     = a0;
            *(uint4*)(vsm + r_ld*128 + (((ko0+1) ^ swr) << 4))     = a1;
            *(uint4*)(vsm + r_ld*128 + (((4+ko0+0) ^ swr) << 4))   = b0;
            *(uint4*)(vsm + r_ld*128 + (((4+ko0+1) ^ swr) << 4))   = b1;
            if (tl < 64) qn_s[tl] = g_qn[nb + tl];
            else         kn_s[tl - 64] = g_kn[nb + tl - 64];
        }
        __syncthreads();

        // ---- S = q k^T ----
        float sf[8][4];
        #pragma unroll
        for (int nt = 0; nt < 8; nt++)
            #pragma unroll
            for (int i = 0; i < 4; i++) sf[nt][i] = 0.f;

        #pragma unroll
        for (int kt = 0; kt < 2; kt++) {
            int lrow = mbase + ((lane >> 3) & 1) * 8 + (lane & 7);
            int ko   = kt*2 + (lane >> 4);
            uint32_t ah[4], al[4];
            ldsm_x4(ah, qsb + lrow*128 + ((ko ^ (lrow & 7)) << 4));
            ldsm_x4(al, qsb + lrow*128 + (((4 + ko) ^ (lrow & 7)) << 4));
            int krow_l = (lane & 7);
            int kko    = kt*2 + ((lane >> 3) & 1);
            uint32_t kbh[8][2], kbl[8][2];
            #pragma unroll
            for (int nt = 0; nt < 8; nt++) {
                int krow = nt*8 + krow_l;
                ldsm_x2(kbh[nt], ksb + krow*128 + ((kko ^ (krow & 7)) << 4));
                ldsm_x2(kbl[nt], ksb + krow*128 + (((4 + kko) ^ (krow & 7)) << 4));
            }
            #pragma unroll
            for (int nt = 0; nt < 8; nt++) mma16816(sf[nt], ah, kbh[nt]);
            #pragma unroll
            for (int nt = 0; nt < 8; nt++) mma16816(sf[nt], ah, kbl[nt]);
            #pragma unroll
            for (int nt = 0; nt < 8; nt++) mma16816(sf[nt], al, kbh[nt]);
        }

        // ---- epilogue: cosine norm + tau + bias + mask ----
        int rA = mbase + (lane >> 2);
        int rB = rA + 8;
        float qnA = qn_s[rA], qnB = qn_s[rB];
        #pragma unroll
        for (int nt = 0; nt < 8; nt++) {
            int c0 = nt*8 + 2*(lane & 3);
            float2 kn2 = *(float2*)&kn_s[c0];
            int iA = rA*64 + c0, iB = rB*64 + c0;
            float2 tA = *(const float2*)(itp + iA);
            float2 tB = *(const float2*)(itp + iB);
            float2 bA = *(const float2*)(bpp + iA);
            float2 bB = *(const float2*)(bpp + iB);
            float2 mA = *(const float2*)(mpp + iA);
            float2 mB = *(const float2*)(mpp + iB);
            sf[nt][0] = __fdividef(sf[nt][0], fmaxf(qnA*kn2.x, 1e-6f)) * tA.x + bA.x + mA.x;
            sf[nt][1] = __fdividef(sf[nt][1], fmaxf(qnA*kn2.y, 1e-6f)) * tA.y + bA.y + mA.y;
            sf[nt][2] = __fdividef(sf[nt][2], fmaxf(qnB*kn2.x, 1e-6f)) * tB.x + bB.x + mB.x;
            sf[nt][3] = __fdividef(sf[nt][3], fmaxf(qnB*kn2.y, 1e-6f)) * tB.y + bB.y + mB.y;
        }

        // ---- fragment softmax ----
        {
            float mA = -1e30f, mB = -1e30f;
            #pragma unroll
            for (int nt = 0; nt < 8; nt++) {
                mA = fmaxf(mA, fmaxf(sf[nt][0], sf[nt][1]));
                mB = fmaxf(mB, fmaxf(sf[nt][2], sf[nt][3]));
            }
            mA = fmaxf(mA, __shfl_xor_sync(0xffffffffu, mA, 1));
            mA = fmaxf(mA, __shfl_xor_sync(0xffffffffu, mA, 2));
            mB = fmaxf(mB, __shfl_xor_sync(0xffffffffu, mB, 1));
            mB = fmaxf(mB, __shfl_xor_sync(0xffffffffu, mB, 2));
            float sA = 0.f, sB = 0.f;
            #pragma unroll
            for (int nt = 0; nt < 8; nt++) {
                sf[nt][0] = __expf(sf[nt][0] - mA); sA += sf[nt][0];
                sf[nt][1] = __expf(sf[nt][1] - mA); sA += sf[nt][1];
                sf[nt][2] = __expf(sf[nt][2] - mB); sB += sf[nt][2];
                sf[nt][3] = __expf(sf[nt][3] - mB); sB += sf[nt][3];
            }
            sA += __shfl_xor_sync(0xffffffffu, sA, 1);
            sA += __shfl_xor_sync(0xffffffffu, sA, 2);
            sB += __shfl_xor_sync(0xffffffffu, sB, 1);
            sB += __shfl_xor_sync(0xffffffffu, sB, 2);
            float iA2 = __fdividef(1.f, sA);
            float iB2 = __fdividef(1.f, sB);
            #pragma unroll
            for (int nt = 0; nt < 8; nt++) {
                sf[nt][0] *= iA2; sf[nt][1] *= iA2;
                sf[nt][2] *= iB2; sf[nt][3] *= iB2;
            }
        }

        // ---- O = P V ----
        float of[4][4];
        #pragma unroll
        for (int nt = 0; nt < 4; nt++)
            #pragma unroll
            for (int i = 0; i < 4; i++) of[nt][i] = 0.f;

        #pragma unroll
        for (int kt2 = 0; kt2 < 4; kt2++) {
            int ntA = 2*kt2, ntB = 2*kt2 + 1;
            uint32_t pah[4], pal[4];
            float r0, r1;
            pah[0] = pack_hi(sf[ntA][0], sf[ntA][1], r0, r1); pal[0] = pack2(r0, r1);
            pah[1] = pack_hi(sf[ntA][2], sf[ntA][3], r0, r1); pal[1] = pack2(r0, r1);
            pah[2] = pack_hi(sf[ntB][0], sf[ntB][1], r0, r1); pal[2] = pack2(r0, r1);
            pah[3] = pack_hi(sf[ntB][2], sf[ntB][3], r0, r1); pal[3] = pack2(r0, r1);
            int vrow = kt2*16 + (lane & 15);
            int vsw = vrow & 7;
            uint32_t vbh[4][2], vbl[4][2];
            #pragma unroll
            for (int nt2 = 0; nt2 < 4; nt2++) {
                ldsm_x2t(vbh[nt2], vsb + vrow*128 + ((nt2 ^ vsw) << 4));
                ldsm_x2t(vbl[nt2], vsb + vrow*128 + (((4 + nt2) ^ vsw) << 4));
            }
            #pragma unroll
            for (int nt2 = 0; nt2 < 4; nt2++) mma16816(of[nt2], pah, vbh[nt2]);
            #pragma unroll
            for (int nt2 = 0; nt2 < 4; nt2++) mma16816(of[nt2], pah, vbl[nt2]);
            #pragma unroll
            for (int nt2 = 0; nt2 < 4; nt2++) mma16816(of[nt2], pal, vbh[nt2]);
        }

        // ---- store O pre-split (bf16 h/l words) ----
        {
            size_t baseA = ((size_t)b*NTOK + rA)*128 + h*16 + (lane & 3);
            size_t baseB = ((size_t)b*NTOK + rB)*128 + h*16 + (lane & 3);
            #pragma unroll
            for (int nt2 = 0; nt2 < 4; nt2++) {
                float rx, ry;
                uint32_t hw = pack_hi(of[nt2][0], of[nt2][1], rx, ry);
                g_aoh[baseA + nt2*4] = hw;
                g_aol[baseA + nt2*4] = pack2(rx, ry);
                hw = pack_hi(of[nt2][2], of[nt2][3], rx, ry);
                g_aoh[baseB + nt2*4] = hw;
                g_aol[baseB + nt2*4] = pack2(rx, ry);
            }
        }
        __syncthreads();
    }
}

// ============================================================
// launch
// ============================================================
extern "C" void kernel_launch(void* const* d_in, const int* in_sizes, int n_in,
                              void* d_out, int out_size)
{
    const float* x      = (const float*)d_in[0];
    const float* KV     = (const float*)d_in[1];
    const float* mask   = (const float*)d_in[2];
    const float* Wq     = (const float*)d_in[3];
    const float* bq     = (const float*)d_in[4];
    const float* Wkv    = (const float*)d_in[5];
    const float* bkv    = (const float*)d_in[6];
    const float* Wp     = (const float*)d_in[7];
    const float* bp     = (const float*)d_in[8];
    const float* cpb_w1 = (const float*)d_in[9];
    const float* cpb_b1 = (const float*)d_in[10];
    const float* cpb_w2 = (const float*)d_in[11];
    const float* cpb_b2 = (const float*)d_in[12];
    const float* tau    = (const float*)d_in[13];
    const float* lri    = (const float*)d_in[14];
    float* out = (float*)d_out;

    const int MT = (BWIN * NTOK) / 128;   // 1024

    cudaFuncSetAttribute(attn_mma_kernel,
                         cudaFuncAttributeMaxDynamicSharedMemorySize, ATTN_SMEM);

    prep_w_kernel<<<1024, 256>>>(Wq, Wkv, Wp);
    bias_kernel<<<(NTOK*NTOK + 255)/256, 256>>>(cpb_w1, cpb_b1, cpb_w2, cpb_b2, tau, lri);
    mma_gemm_kernel<0><<<dim3(2, MT), 256>>>(x,  bq,  nullptr, 256, 0);
    mma_gemm_kernel<1><<<dim3(4, MT), 256>>>(KV, bkv, nullptr, 512, 65536);
    attn_mma_kernel<<<dim3(256, HEADS), 256, ATTN_SMEM>>>(mask);
    mma_gemm_kernel<2><<<dim3(2, MT), 256>>>(nullptr, bp, out, 256, 196608);
}

// round 11
// speedup vs baseline: 1.1010x; 1.1010x over previous
#include <cuda_runtime.h>
#include <cuda_bf16.h>
#include <cstdint>

#define BWIN 2048
#define NTOK 64
#define DIM  256
#define HEADS 8
#define HD   32
#define NW   64

// ---- scratch (device globals; no allocations allowed) ----
__device__ uint32_t g_qh[BWIN*HEADS*NTOK*16];
__device__ uint32_t g_ql[BWIN*HEADS*NTOK*16];
__device__ uint32_t g_kh[BWIN*HEADS*NTOK*16];
__device__ uint32_t g_kl[BWIN*HEADS*NTOK*16];
__device__ uint32_t g_vh[BWIN*HEADS*NTOK*16];
__device__ uint32_t g_vl[BWIN*HEADS*NTOK*16];
__device__ float    g_qn[BWIN*HEADS*NTOK];
__device__ float    g_kn[BWIN*HEADS*NTOK];
__device__ float g_ao[BWIN*NTOK*DIM];
__device__ float g_bias  [HEADS*NTOK*NTOK];
__device__ float g_invtau[HEADS*NTOK*NTOK];
__device__ __nv_bfloat16 g_wbh[262144];
__device__ __nv_bfloat16 g_wbl[262144];

// ============================================================
// helpers
// ============================================================
__device__ __forceinline__ void mma16816(float* c, const uint32_t* a, const uint32_t* b) {
    asm volatile("mma.sync.aligned.m16n8k16.row.col.f32.bf16.bf16.f32 "
        "{%0,%1,%2,%3}, {%4,%5,%6,%7}, {%8,%9}, {%0,%1,%2,%3};\n"
        : "+f"(c[0]), "+f"(c[1]), "+f"(c[2]), "+f"(c[3])
        : "r"(a[0]), "r"(a[1]), "r"(a[2]), "r"(a[3]), "r"(b[0]), "r"(b[1]));
}
__device__ __forceinline__ void ldsm_x4(uint32_t* r, uint32_t addr) {
    asm volatile("ldmatrix.sync.aligned.m8n8.x4.shared.b16 {%0,%1,%2,%3}, [%4];"
        : "=r"(r[0]), "=r"(r[1]), "=r"(r[2]), "=r"(r[3]) : "r"(addr));
}
__device__ __forceinline__ void ldsm_x2(uint32_t* r, uint32_t addr) {
    asm volatile("ldmatrix.sync.aligned.m8n8.x2.shared.b16 {%0,%1}, [%2];"
        : "=r"(r[0]), "=r"(r[1]) : "r"(addr));
}
__device__ __forceinline__ void ldsm_x2t(uint32_t* r, uint32_t addr) {
    asm volatile("ldmatrix.sync.aligned.m8n8.x2.trans.shared.b16 {%0,%1}, [%2];"
        : "=r"(r[0]), "=r"(r[1]) : "r"(addr));
}
__device__ __forceinline__ void cp16(uint32_t smem, const void* gmem) {
    asm volatile("cp.async.cg.shared.global [%0], [%1], 16;" :: "r"(smem), "l"(gmem));
}
__device__ __forceinline__ void cp_commit() { asm volatile("cp.async.commit_group;"); }
__device__ __forceinline__ void cp_wait0()  { asm volatile("cp.async.wait_group 0;"); }
__device__ __forceinline__ uint32_t pack_hi(float a, float b, float& ra, float& rb) {
    __nv_bfloat16 ha = __float2bfloat16_rn(a);
    __nv_bfloat16 hb = __float2bfloat16_rn(b);
    ra = a - __bfloat162float(ha);
    rb = b - __bfloat162float(hb);
    return ((uint32_t)__bfloat16_as_ushort(hb) << 16) | (uint32_t)__bfloat16_as_ushort(ha);
}
__device__ __forceinline__ uint32_t pack2(float a, float b) {
    return ((uint32_t)__bfloat16_as_ushort(__float2bfloat16_rn(b)) << 16)
         | (uint32_t)__bfloat16_as_ushort(__float2bfloat16_rn(a));
}

// ============================================================
// Kernel 0: pre-split weights to bf16 h/l ([K,N] layout)
// ============================================================
__global__ void prep_w_kernel(const float* __restrict__ Wq,
                              const float* __restrict__ Wkv,
                              const float* __restrict__ Wp)
{
    int i = blockIdx.x * 256 + threadIdx.x;
    if (i >= 262144) return;
    float f;
    if (i < 65536) f = Wq[i];
    else if (i < 196608) f = Wkv[i - 65536];
    else f = Wp[i - 196608];
    __nv_bfloat16 hh = __float2bfloat16_rn(f);
    g_wbh[i] = hh;
    g_wbl[i] = __float2bfloat16_rn(f - __bfloat162float(hh));
}

// ============================================================
// Kernel 1: CPB bias MLP + inv-tau tables
// ============================================================
__global__ void bias_kernel(const float* __restrict__ w1, const float* __restrict__ b1,
                            const float* __restrict__ w2, const float* __restrict__ b2,
                            const float* __restrict__ tau, const float* __restrict__ lri)
{
    int idx = blockIdx.x * blockDim.x + threadIdx.x;
    if (idx >= NTOK*NTOK) return;
    float r0 = lri[idx*2 + 0];
    float r1 = lri[idx*2 + 1];
    float acc[HEADS];
    #pragma unroll
    for (int h = 0; h < HEADS; h++) acc[h] = 0.f;
    for (int k = 0; k < 256; k++) {
        float hk = fmaxf(r0 * w1[k] + r1 * w1[256 + k] + b1[k], 0.f);
        #pragma unroll
        for (int h = 0; h < HEADS; h++) acc[h] += hk * w2[k*HEADS + h];
    }
    #pragma unroll
    for (int h = 0; h < HEADS; h++) {
        g_bias[h*NTOK*NTOK + idx] = acc[h] + b2[h];
        g_invtau[h*NTOK*NTOK + idx] = 1.0f / fmaxf(tau[h*NTOK*NTOK + idx], 0.01f);
    }
}

// ============================================================
// Kernel 2a: fused Q+KV projection GEMM (R8 body; mode by blockIdx.x)
//   bx 0-1: Q (mode 0), bx 2-5: KV (mode 1)
// ============================================================
__global__ void __launch_bounds__(256, 2) qkv_gemm_kernel(
    const float* __restrict__ Aq, const float* __restrict__ Akv,
    const float* __restrict__ bq, const float* __restrict__ bkv)
{
    __shared__ alignas(16) char Bs_h[2][4096];
    __shared__ alignas(16) char Bs_l[2][4096];

    int bx = blockIdx.x;
    int mode = (bx < 2) ? 0 : 1;
    const float* A = (mode == 0) ? Aq : Akv;
    const float* bias = (mode == 0) ? bq : bkv;
    int ldb  = (mode == 0) ? 256 : 512;
    int woff = (mode == 0) ? 0 : 65536;
    int col0 = ((mode == 0) ? bx : bx - 2) * 128;

    int tid = threadIdx.x;
    int lane = tid & 31, wid = tid >> 5;
    int warp_m = wid >> 1, warp_n = wid & 1;
    int row0 = blockIdx.y * 128;

    int k_b2 = tid >> 4;
    int n_b2 = (tid & 15) * 8;
    uint32_t offB = (uint32_t)k_b2*256u + (uint32_t)(((n_b2 >> 3) ^ (k_b2 & 7)) << 4);
    uint32_t stBh[2], stBl[2];
    #pragma unroll
    for (int s = 0; s < 2; s++) {
        stBh[s] = (uint32_t)__cvta_generic_to_shared(&Bs_h[s][0]) + offB;
        stBl[s] = (uint32_t)__cvta_generic_to_shared(&Bs_l[s][0]) + offB;
    }
    int bk_lane = lane & 15;
    uint32_t bbase_h[2], bbase_l[2];
    #pragma unroll
    for (int s = 0; s < 2; s++) {
        bbase_h[s] = (uint32_t)__cvta_generic_to_shared(&Bs_h[s][0]) + (uint32_t)bk_lane * 256u;
        bbase_l[s] = (uint32_t)__cvta_generic_to_shared(&Bs_l[s][0]) + (uint32_t)bk_lane * 256u;
    }
    int bkm = bk_lane & 7;

    const __nv_bfloat16* Bh = g_wbh + woff;
    const __nv_bfloat16* Bl = g_wbl + woff;

    const float* ap0 = A + (size_t)(row0 + warp_m*32 + (lane >> 2)) * DIM + (lane & 3) * 2;
    const float* ap1 = ap0 + 16 * DIM;

    float acc[2][8][4];
    #pragma unroll
    for (int mt = 0; mt < 2; mt++)
        #pragma unroll
        for (int nt = 0; nt < 8; nt++)
            #pragma unroll
            for (int i = 0; i < 4; i++) acc[mt][nt][i] = 0.f;

    float2 af[2][4];
#define LDA(kc)                                                         \
    {                                                                   \
        int kk = (kc) * 16;                                             \
        af[0][0] = *(const float2*)(ap0 + kk);                          \
        af[0][1] = *(const float2*)(ap0 + 8*DIM + kk);                  \
        af[0][2] = *(const float2*)(ap0 + kk + 8);                      \
        af[0][3] = *(const float2*)(ap0 + 8*DIM + kk + 8);              \
        af[1][0] = *(const float2*)(ap1 + kk);                          \
        af[1][1] = *(const float2*)(ap1 + 8*DIM + kk);                  \
        af[1][2] = *(const float2*)(ap1 + kk + 8);                      \
        af[1][3] = *(const float2*)(ap1 + 8*DIM + kk + 8);              \
    }

    cp16(stBh[0], Bh + (size_t)k_b2 * ldb + col0 + n_b2);
    cp16(stBl[0], Bl + (size_t)k_b2 * ldb + col0 + n_b2);
    cp_commit();
    LDA(0);
    cp_wait0();
    __syncthreads();

    for (int kc = 0; kc < DIM/16; kc++) {
        int cur = kc & 1, nxt = cur ^ 1;
        bool has_next = (kc + 1 < DIM/16);

        if (has_next) {
            int k0 = (kc + 1) * 16;
            cp16(stBh[nxt], Bh + (size_t)(k0 + k_b2) * ldb + col0 + n_b2);
            cp16(stBl[nxt], Bl + (size_t)(k0 + k_b2) * ldb + col0 + n_b2);
            cp_commit();
        }

        uint32_t ah[2][4], al[2][4];
        #pragma unroll
        for (int mt = 0; mt < 2; mt++)
            #pragma unroll
            for (int j = 0; j < 4; j++) {
                float rx, ry;
                ah[mt][j] = pack_hi(af[mt][j].x, af[mt][j].y, rx, ry);
                al[mt][j] = pack2(rx, ry);
            }

        if (has_next) LDA(kc + 1);

        #pragma unroll
        for (int nt = 0; nt < 8; nt++) {
            uint32_t boff = (uint32_t)(((warp_n*8 + nt) ^ bkm) << 4);
            uint32_t bh2[2], bl2[2];
            ldsm_x2t(bh2, bbase_h[cur] + boff);
            ldsm_x2t(bl2, bbase_l[cur] + boff);
            mma16816(acc[0][nt], ah[0], bh2);
            mma16816(acc[1][nt], ah[1], bh2);
            mma16816(acc[0][nt], ah[0], bl2);
            mma16816(acc[1][nt], ah[1], bl2);
            mma16816(acc[0][nt], al[0], bh2);
            mma16816(acc[1][nt], al[1], bh2);
        }

        if (has_next) cp_wait0();
        __syncthreads();
    }
#undef LDA

    // ---- epilogue: pack bf16 h/l + fused row norms ----
    const float scale = 0.17677669529663687f;
    #pragma unroll
    for (int mt = 0; mt < 2; mt++) {
        int rr = row0 + warp_m*32 + mt*16 + (lane >> 2);
        int bI = rr >> 6, nI = rr & 63;
        #pragma unroll
        for (int hg = 0; hg < 2; hg++) {
            int cg = col0 + warp_n*64 + hg*32;
            float sqA = 0.f, sqB = 0.f;
            uint32_t hwA[4], lwA[4], hwB[4], lwB[4];
            #pragma unroll
            for (int j = 0; j < 4; j++) {
                int nt = hg*4 + j;
                int c = cg + j*8 + 2*(lane & 3);
                float b0 = bias[c], b1 = bias[c+1];
                float v0 = acc[mt][nt][0]+b0, v1 = acc[mt][nt][1]+b1;
                float v2 = acc[mt][nt][2]+b0, v3 = acc[mt][nt][3]+b1;
                if (mode == 0) { v0*=scale; v1*=scale; v2*=scale; v3*=scale; }
                sqA += v0*v0 + v1*v1;
                sqB += v2*v2 + v3*v3;
                float rx, ry;
                hwA[j] = pack_hi(v0, v1, rx, ry); lwA[j] = pack2(rx, ry);
                hwB[j] = pack_hi(v2, v3, rx, ry); lwB[j] = pack2(rx, ry);
            }
            sqA += __shfl_xor_sync(0xffffffffu, sqA, 1);
            sqA += __shfl_xor_sync(0xffffffffu, sqA, 2);
            sqB += __shfl_xor_sync(0xffffffffu, sqB, 1);
            sqB += __shfl_xor_sync(0xffffffffu, sqB, 2);

            uint32_t *dh, *dl;
            float* dn = nullptr;
            int hh;
            if (mode == 0)      { hh = cg >> 5;         dh = g_qh; dl = g_ql; dn = g_qn; }
            else if (cg < 256)  { hh = cg >> 5;         dh = g_kh; dl = g_kl; dn = g_kn; }
            else                { hh = (cg - 256) >> 5; dh = g_vh; dl = g_vl; }

            size_t wb = (((size_t)bI*HEADS + hh)*NTOK + nI)*16 + (lane & 3);
            #pragma unroll
            for (int j = 0; j < 4; j++) {
                dh[wb + j*4]        = hwA[j];
                dl[wb + j*4]        = lwA[j];
                dh[wb + 8*16 + j*4] = hwB[j];
                dl[wb + 8*16 + j*4] = lwB[j];
            }
            if (dn && (lane & 3) == 0) {
                size_t nb = ((size_t)bI*HEADS + hh)*NTOK + nI;
                dn[nb]     = sqrtf(sqA);
                dn[nb + 8] = sqrtf(sqB);
            }
        }
    }
}

// ============================================================
// Kernel 2b: output projection GEMM (R8 mode-2 path)
// ============================================================
__global__ void __launch_bounds__(256, 2) p_gemm_kernel(
    const float* __restrict__ bias, float* __restrict__ D)
{
    __shared__ alignas(16) char Bs_h[2][4096];
    __shared__ alignas(16) char Bs_l[2][4096];

    const float* A = g_ao;
    int tid = threadIdx.x;
    int lane = tid & 31, wid = tid >> 5;
    int warp_m = wid >> 1, warp_n = wid & 1;
    int row0 = blockIdx.y * 128;
    int col0 = blockIdx.x * 128;
    const int ldb = 256;

    int k_b2 = tid >> 4;
    int n_b2 = (tid & 15) * 8;
    uint32_t offB = (uint32_t)k_b2*256u + (uint32_t)(((n_b2 >> 3) ^ (k_b2 & 7)) << 4);
    uint32_t stBh[2], stBl[2];
    #pragma unroll
    for (int s = 0; s < 2; s++) {
        stBh[s] = (uint32_t)__cvta_generic_to_shared(&Bs_h[s][0]) + offB;
        stBl[s] = (uint32_t)__cvta_generic_to_shared(&Bs_l[s][0]) + offB;
    }
    int bk_lane = lane & 15;
    uint32_t bbase_h[2], bbase_l[2];
    #pragma unroll
    for (int s = 0; s < 2; s++) {
        bbase_h[s] = (uint32_t)__cvta_generic_to_shared(&Bs_h[s][0]) + (uint32_t)bk_lane * 256u;
        bbase_l[s] = (uint32_t)__cvta_generic_to_shared(&Bs_l[s][0]) + (uint32_t)bk_lane * 256u;
    }
    int bkm = bk_lane & 7;

    const __nv_bfloat16* Bh = g_wbh + 196608;
    const __nv_bfloat16* Bl = g_wbl + 196608;

    const float* ap0 = A + (size_t)(row0 + warp_m*32 + (lane >> 2)) * DIM + (lane & 3) * 2;
    const float* ap1 = ap0 + 16 * DIM;

    float acc[2][8][4];
    #pragma unroll
    for (int mt = 0; mt < 2; mt++)
        #pragma unroll
        for (int nt = 0; nt < 8; nt++)
            #pragma unroll
            for (int i = 0; i < 4; i++) acc[mt][nt][i] = 0.f;

    float2 af[2][4];
#define LDA(kc)                                                         \
    {                                                                   \
        int kk = (kc) * 16;                                             \
        af[0][0] = *(const float2*)(ap0 + kk);                          \
        af[0][1] = *(const float2*)(ap0 + 8*DIM + kk);                  \
        af[0][2] = *(const float2*)(ap0 + kk + 8);                      \
        af[0][3] = *(const float2*)(ap0 + 8*DIM + kk + 8);              \
        af[1][0] = *(const float2*)(ap1 + kk);                          \
        af[1][1] = *(const float2*)(ap1 + 8*DIM + kk);                  \
        af[1][2] = *(const float2*)(ap1 + kk + 8);                      \
        af[1][3] = *(const float2*)(ap1 + 8*DIM + kk + 8);              \
    }

    cp16(stBh[0], Bh + (size_t)k_b2 * ldb + col0 + n_b2);
    cp16(stBl[0], Bl + (size_t)k_b2 * ldb + col0 + n_b2);
    cp_commit();
    LDA(0);
    cp_wait0();
    __syncthreads();

    for (int kc = 0; kc < DIM/16; kc++) {
        int cur = kc & 1, nxt = cur ^ 1;
        bool has_next = (kc + 1 < DIM/16);

        if (has_next) {
            int k0 = (kc + 1) * 16;
            cp16(stBh[nxt], Bh + (size_t)(k0 + k_b2) * ldb + col0 + n_b2);
            cp16(stBl[nxt], Bl + (size_t)(k0 + k_b2) * ldb + col0 + n_b2);
            cp_commit();
        }

        uint32_t ah[2][4], al[2][4];
        #pragma unroll
        for (int mt = 0; mt < 2; mt++)
            #pragma unroll
            for (int j = 0; j < 4; j++) {
                float rx, ry;
                ah[mt][j] = pack_hi(af[mt][j].x, af[mt][j].y, rx, ry);
                al[mt][j] = pack2(rx, ry);
            }

        if (has_next) LDA(kc + 1);

        #pragma unroll
        for (int nt = 0; nt < 8; nt++) {
            uint32_t boff = (uint32_t)(((warp_n*8 + nt) ^ bkm) << 4);
            uint32_t bh2[2], bl2[2];
            ldsm_x2t(bh2, bbase_h[cur] + boff);
            ldsm_x2t(bl2, bbase_l[cur] + boff);
            mma16816(acc[0][nt], ah[0], bh2);
            mma16816(acc[1][nt], ah[1], bh2);
            mma16816(acc[0][nt], ah[0], bl2);
            mma16816(acc[1][nt], ah[1], bl2);
            mma16816(acc[0][nt], al[0], bh2);
            mma16816(acc[1][nt], al[1], bh2);
        }

        if (has_next) cp_wait0();
        __syncthreads();
    }
#undef LDA

    #pragma unroll
    for (int mt = 0; mt < 2; mt++) {
        int r_base = row0 + warp_m*32 + mt*16 + (lane >> 2);
        #pragma unroll
        for (int nt = 0; nt < 8; nt++) {
            int c = col0 + warp_n*64 + nt*8 + 2*(lane & 3);
            float b0 = bias[c], b1 = bias[c+1];
            *(float2*)&D[(size_t)r_base*DIM + c] =
                make_float2(acc[mt][nt][0]+b0, acc[mt][nt][1]+b1);
            *(float2*)&D[(size_t)(r_base+8)*DIM + c] =
                make_float2(acc[mt][nt][2]+b0, acc[mt][nt][3]+b1);
        }
    }
}

// ============================================================
// Kernel 3: tensor-core attention — one window-tile per CTA
// ============================================================
__global__ void __launch_bounds__(128) attn_mma_kernel(const float* __restrict__ mask)
{
    __shared__ alignas(16) char qsm[8192];
    __shared__ alignas(16) char ksm[8192];
    __shared__ alignas(16) char vsm[8192];
    __shared__ float qn_s[NTOK], kn_s[NTOK];

    int b = blockIdx.x;                  // 0..2047 (window index)
    int h = blockIdx.y;
    int w = b & 63;
    int tid = threadIdx.x;
    int lane = tid & 31, wid = tid >> 5;
    int mbase = wid * 16;

    uint32_t qsb = (uint32_t)__cvta_generic_to_shared(qsm);
    uint32_t ksb = (uint32_t)__cvta_generic_to_shared(ksm);
    uint32_t vsb = (uint32_t)__cvta_generic_to_shared(vsm);

    const float* itp = g_invtau + h*4096;
    const float* bpp = g_bias   + h*4096;
    const float* mpp = mask + (size_t)w*4096;

    int r_ld = tid >> 1;
    int half = tid & 1;
    int swr = r_ld & 7;
    int ko0 = half * 2;

    size_t wb = (((size_t)b*HEADS + h)*NTOK + r_ld)*16 + half*8;
    size_t nb = ((size_t)b*HEADS + h)*NTOK;

    // ---- fill: packed copies + norm loads ----
    {
        uint4 a0 = *(const uint4*)(g_qh + wb);
        uint4 a1 = *(const uint4*)(g_qh + wb + 4);
        uint4 b0 = *(const uint4*)(g_ql + wb);
        uint4 b1 = *(const uint4*)(g_ql + wb + 4);
        *(uint4*)(qsm + r_ld*128 + (((ko0+0) ^ swr) << 4))     = a0;
        *(uint4*)(qsm + r_ld*128 + (((ko0+1) ^ swr) << 4))     = a1;
        *(uint4*)(qsm + r_ld*128 + (((4+ko0+0) ^ swr) << 4))   = b0;
        *(uint4*)(qsm + r_ld*128 + (((4+ko0+1) ^ swr) << 4))   = b1;
        a0 = *(const uint4*)(g_kh + wb);
        a1 = *(const uint4*)(g_kh + wb + 4);
        b0 = *(const uint4*)(g_kl + wb);
        b1 = *(const uint4*)(g_kl + wb + 4);
        *(uint4*)(ksm + r_ld*128 + (((ko0+0) ^ swr) << 4))     = a0;
        *(uint4*)(ksm + r_ld*128 + (((ko0+1) ^ swr) << 4))     = a1;
        *(uint4*)(ksm + r_ld*128 + (((4+ko0+0) ^ swr) << 4))   = b0;
        *(uint4*)(ksm + r_ld*128 + (((4+ko0+1) ^ swr) << 4))   = b1;
        a0 = *(const uint4*)(g_vh + wb);
        a1 = *(const uint4*)(g_vh + wb + 4);
        b0 = *(const uint4*)(g_vl + wb);
        b1 = *(const uint4*)(g_vl + wb + 4);
        *(uint4*)(vsm + r_ld*128 + (((ko0+0) ^ swr) << 4))     = a0;
        *(uint4*)(vsm + r_ld*128 + (((ko0+1) ^ swr) << 4))     = a1;
        *(uint4*)(vsm + r_ld*128 + (((4+ko0+0) ^ swr) << 4))   = b0;
        *(uint4*)(vsm + r_ld*128 + (((4+ko0+1) ^ swr) << 4))   = b1;
        if (tid < 64) qn_s[tid] = g_qn[nb + tid];
        else          kn_s[tid - 64] = g_kn[nb + tid - 64];
    }
    __syncthreads();

    // ---- S = q k^T ----
    float sf[8][4];
    #pragma unroll
    for (int nt = 0; nt < 8; nt++)
        #pragma unroll
        for (int i = 0; i < 4; i++) sf[nt][i] = 0.f;

    #pragma unroll
    for (int kt = 0; kt < 2; kt++) {
        int lrow = mbase + ((lane >> 3) & 1) * 8 + (lane & 7);
        int ko   = kt*2 + (lane >> 4);
        uint32_t ah[4], al[4];
        ldsm_x4(ah, qsb + lrow*128 + ((ko ^ (lrow & 7)) << 4));
        ldsm_x4(al, qsb + lrow*128 + (((4 + ko) ^ (lrow & 7)) << 4));
        int krow_l = (lane & 7);
        int kko    = kt*2 + ((lane >> 3) & 1);
        uint32_t kbh[8][2], kbl[8][2];
        #pragma unroll
        for (int nt = 0; nt < 8; nt++) {
            int krow = nt*8 + krow_l;
            ldsm_x2(kbh[nt], ksb + krow*128 + ((kko ^ (krow & 7)) << 4));
            ldsm_x2(kbl[nt], ksb + krow*128 + (((4 + kko) ^ (krow & 7)) << 4));
        }
        #pragma unroll
        for (int nt = 0; nt < 8; nt++) mma16816(sf[nt], ah, kbh[nt]);
        #pragma unroll
        for (int nt = 0; nt < 8; nt++) mma16816(sf[nt], ah, kbl[nt]);
        #pragma unroll
        for (int nt = 0; nt < 8; nt++) mma16816(sf[nt], al, kbh[nt]);
    }

    // ---- epilogue: cosine norm + tau + bias + mask ----
    int rA = mbase + (lane >> 2);
    int rB = rA + 8;
    float qnA = qn_s[rA], qnB = qn_s[rB];
    #pragma unroll
    for (int nt = 0; nt < 8; nt++) {
        int c0 = nt*8 + 2*(lane & 3);
        float2 kn2 = *(float2*)&kn_s[c0];
        int iA = rA*64 + c0, iB = rB*64 + c0;
        float2 tA = *(const float2*)(itp + iA);
        float2 tB = *(const float2*)(itp + iB);
        float2 bA = *(const float2*)(bpp + iA);
        float2 bB = *(const float2*)(bpp + iB);
        float2 mA = *(const float2*)(mpp + iA);
        float2 mB = *(const float2*)(mpp + iB);
        sf[nt][0] = __fdividef(sf[nt][0], fmaxf(qnA*kn2.x, 1e-6f)) * tA.x + bA.x + mA.x;
        sf[nt][1] = __fdividef(sf[nt][1], fmaxf(qnA*kn2.y, 1e-6f)) * tA.y + bA.y + mA.y;
        sf[nt][2] = __fdividef(sf[nt][2], fmaxf(qnB*kn2.x, 1e-6f)) * tB.x + bB.x + mB.x;
        sf[nt][3] = __fdividef(sf[nt][3], fmaxf(qnB*kn2.y, 1e-6f)) * tB.y + bB.y + mB.y;
    }

    // ---- fragment softmax ----
    {
        float mA = -1e30f, mB = -1e30f;
        #pragma unroll
        for (int nt = 0; nt < 8; nt++) {
            mA = fmaxf(mA, fmaxf(sf[nt][0], sf[nt][1]));
            mB = fmaxf(mB, fmaxf(sf[nt][2], sf[nt][3]));
        }
        mA = fmaxf(mA, __shfl_xor_sync(0xffffffffu, mA, 1));
        mA = fmaxf(mA, __shfl_xor_sync(0xffffffffu, mA, 2));
        mB = fmaxf(mB, __shfl_xor_sync(0xffffffffu, mB, 1));
        mB = fmaxf(mB, __shfl_xor_sync(0xffffffffu, mB, 2));
        float sA = 0.f, sB = 0.f;
        #pragma unroll
        for (int nt = 0; nt < 8; nt++) {
            sf[nt][0] = __expf(sf[nt][0] - mA); sA += sf[nt][0];
            sf[nt][1] = __expf(sf[nt][1] - mA); sA += sf[nt][1];
            sf[nt][2] = __expf(sf[nt][2] - mB); sB += sf[nt][2];
            sf[nt][3] = __expf(sf[nt][3] - mB); sB += sf[nt][3];
        }
        sA += __shfl_xor_sync(0xffffffffu, sA, 1);
        sA += __shfl_xor_sync(0xffffffffu, sA, 2);
        sB += __shfl_xor_sync(0xffffffffu, sB, 1);
        sB += __shfl_xor_sync(0xffffffffu, sB, 2);
        float iA2 = __fdividef(1.f, sA);
        float iB2 = __fdividef(1.f, sB);
        #pragma unroll
        for (int nt = 0; nt < 8; nt++) {
            sf[nt][0] *= iA2; sf[nt][1] *= iA2;
            sf[nt][2] *= iB2; sf[nt][3] *= iB2;
        }
    }

    // ---- O = P V ----
    float of[4][4];
    #pragma unroll
    for (int nt = 0; nt < 4; nt++)
        #pragma unroll
        for (int i = 0; i < 4; i++) of[nt][i] = 0.f;

    #pragma unroll
    for (int kt2 = 0; kt2 < 4; kt2++) {
        int ntA = 2*kt2, ntB = 2*kt2 + 1;
        uint32_t pah[4], pal[4];
        float r0, r1;
        pah[0] = pack_hi(sf[ntA][0], sf[ntA][1], r0, r1); pal[0] = pack2(r0, r1);
        pah[1] = pack_hi(sf[ntA][2], sf[ntA][3], r0, r1); pal[1] = pack2(r0, r1);
        pah[2] = pack_hi(sf[ntB][0], sf[ntB][1], r0, r1); pal[2] = pack2(r0, r1);
        pah[3] = pack_hi(sf[ntB][2], sf[ntB][3], r0, r1); pal[3] = pack2(r0, r1);
        int vrow = kt2*16 + (lane & 15);
        int vsw = vrow & 7;
        uint32_t vbh[4][2], vbl[4][2];
        #pragma unroll
        for (int nt2 = 0; nt2 < 4; nt2++) {
            ldsm_x2t(vbh[nt2], vsb + vrow*128 + ((nt2 ^ vsw) << 4));
            ldsm_x2t(vbl[nt2], vsb + vrow*128 + (((4 + nt2) ^ vsw) << 4));
        }
        #pragma unroll
        for (int nt2 = 0; nt2 < 4; nt2++) mma16816(of[nt2], pah, vbh[nt2]);
        #pragma unroll
        for (int nt2 = 0; nt2 < 4; nt2++) mma16816(of[nt2], pah, vbl[nt2]);
        #pragma unroll
        for (int nt2 = 0; nt2 < 4; nt2++) mma16816(of[nt2], pal, vbh[nt2]);
    }

    // ---- store O ----
    {
        float* ob = g_ao + ((size_t)b*NTOK)*DIM + h*HD;
        #pragma unroll
        for (int nt2 = 0; nt2 < 4; nt2++) {
            int c = nt2*8 + 2*(lane & 3);
            *(float2*)(ob + (size_t)rA*DIM + c) = make_float2(of[nt2][0], of[nt2][1]);
            *(float2*)(ob + (size_t)rB*DIM + c) = make_float2(of[nt2][2], of[nt2][3]);
        }
    }
}

// ============================================================
// launch
// ============================================================
extern "C" void kernel_launch(void* const* d_in, const int* in_sizes, int n_in,
                              void* d_out, int out_size)
{
    const float* x      = (const float*)d_in[0];
    const float* KV     = (const float*)d_in[1];
    const float* mask   = (const float*)d_in[2];
    const float* Wq     = (const float*)d_in[3];
    const float* bq     = (const float*)d_in[4];
    const float* Wkv    = (const float*)d_in[5];
    const float* bkv    = (const float*)d_in[6];
    const float* Wp     = (const float*)d_in[7];
    const float* bp     = (const float*)d_in[8];
    const float* cpb_w1 = (const float*)d_in[9];
    const float* cpb_b1 = (const float*)d_in[10];
    const float* cpb_w2 = (const float*)d_in[11];
    const float* cpb_b2 = (const float*)d_in[12];
    const float* tau    = (const float*)d_in[13];
    const float* lri    = (const float*)d_in[14];
    float* out = (float*)d_out;

    const int MT = (BWIN * NTOK) / 128;   // 1024

    prep_w_kernel<<<1024, 256>>>(Wq, Wkv, Wp);
    bias_kernel<<<(NTOK*NTOK + 255)/256, 256>>>(cpb_w1, cpb_b1, cpb_w2, cpb_b2, tau, lri);
    qkv_gemm_kernel<<<dim3(6, MT), 256>>>(x, KV, bq, bkv);
    attn_mma_kernel<<<dim3(BWIN, HEADS), 128>>>(mask);
    p_gemm_kernel<<<dim3(2, MT), 256>>>(bp, out);
}